// round 15
// baseline (speedup 1.0000x reference)
#include <cuda_runtime.h>

#define BB 16
#define CIN 256
#define FF 76
#define NPIX (FF*FF)          /* 5776 */
#define NA 3
#define NCH 85
#define KK 50
#define PXB 160               /* pixels per block */
#define TPB 256               /* 8 warps; 240 conv threads (3a x 4q x 20g) */
#define NG 20                 /* 8-pixel groups per block */
#define NBLK 37
#define TOTB (NBLK*BB)        /* 592 = 148*4 exactly */
#define ST4 (NPIX/4)          /* 1444 ulonglong2 per channel */
#define WQ 66                 /* padded quarter stride (ull): 16B-aligned, bank-split */

typedef unsigned long long ull;

__device__ double       g_acc[5];
__device__ unsigned int g_done;

__constant__ float c_AW[9] = {1.25f,2.0f,4.125f,3.75f,7.75f,7.375f,14.5f,19.5f,46.625f};
__constant__ float c_AH[9] = {1.625f,3.75f,2.875f,7.625f,5.625f,14.875f,11.25f,24.75f,40.75f};
__constant__ float c_MW[3] = {1.25f,2.0f,4.125f};
__constant__ float c_MH[3] = {1.625f,3.75f,2.875f};

/* union: w2 (conv phase) -> part (combine phase) */
union UShared {
    ull w2[15][4*WQ];           /* 31680 B, quarter-interleaved+pad */
    ull part[4][15][NG][4];     /* 38400 B */
};
struct SMem {
    UShared u;
    float  out5[NA][PXB][5];    /* 9600 B */
    float  sB[15];
    float  sTx[KK], sTy[KK], sTw[KK], sTh[KK];
    float  sX1[KK], sY1[KK], sX2[KK], sY2[KK], sAr[KK];
    int    sCls[KK];
    int    sOwn[NA*PXB];
    int    sPos[KK];
    int    sCnt;
    float  sX[CIN];
    double red[5][8];
};

__device__ __forceinline__ float sigf(float x){ return 1.0f/(1.0f + expf(-x)); }

__device__ __forceinline__ float bce1(float p, float t){
    float pc = fminf(fmaxf(p, 1e-12f), 0.99999988f);
    return -(t*logf(pc) + (1.0f - t)*logf(1.0f - pc));
}

__device__ __forceinline__ void fma2(ull& acc, ull a, ull b){
    asm("fma.rn.f32x2 %0, %1, %2, %0;" : "+l"(acc) : "l"(a), "l"(b));
}
__device__ __forceinline__ ull add2(ull a, ull b){
    ull r; asm("add.rn.f32x2 %0, %1, %2;" : "=l"(r) : "l"(a), "l"(b)); return r;
}
__device__ __forceinline__ float2 u2f2(ull v){
    float2 r; asm("mov.b64 {%0, %1}, %2;" : "=f"(r.x), "=f"(r.y) : "l"(v)); return r;
}

__global__ void __launch_bounds__(TPB, 4)
k_main(const float* __restrict__ xin, const float* __restrict__ labels,
       const float* __restrict__ cw,  const float* __restrict__ cb,
       float* __restrict__ dout)
{
    extern __shared__ __align__(16) char smraw[];
    SMem* sm = reinterpret_cast<SMem*>(smraw);

    int tid = threadIdx.x;
    int b   = blockIdx.y;
    int n0  = blockIdx.x*PXB;
    int npb = NPIX - n0; if (npb > PXB) npb = PXB;   /* 160 or 16 */

    for (int i = tid; i < NA*PXB; i += TPB) sm->sOwn[i] = -1;
    if (tid == 0) sm->sCnt = 0;

    /* weights as (w,w) pairs, quarter-interleaved+padded */
    for (int i = tid; i < 15*CIN; i += TPB){
        int j = i >> 8, c = i & 255;
        int a = j/5, ch = j%5;
        float w = cw[(a*NCH + ch)*CIN + c];
        float2 p = make_float2(w, w);
        sm->u.w2[j][(c >> 6)*WQ + (c & 63)] = *reinterpret_cast<ull*>(&p);
    }
    if (tid < 15){ int a = tid/5, ch = tid%5; sm->sB[tid] = cb[a*NCH + ch]; }
    if (tid >= 64 && tid < 64 + KK){
        int t = tid - 64;
        const float* L = labels + (b*KK + t)*5;
        float cls=L[0], xc=L[1], yc=L[2], w=L[3], h=L[4];
        bool valid = (cls + xc + yc + w + h) > 0.0f;
        float tx = xc*(float)FF, ty = yc*(float)FF;
        float tw = w *(float)FF, th = h *(float)FF;
        sm->sTx[t]=tx; sm->sTy[t]=ty; sm->sTw[t]=tw; sm->sTh[t]=th;
        sm->sCls[t] = (int)cls;
        if (valid){
            sm->sX1[t]=tx-tw*0.5f; sm->sY1[t]=ty-th*0.5f;
            sm->sX2[t]=tx+tw*0.5f; sm->sY2[t]=ty+th*0.5f;
            sm->sAr[t]=tw*th;
        } else {
            sm->sX1[t]= 3.0e38f; sm->sY1[t]= 3.0e38f;
            sm->sX2[t]=-3.0e38f; sm->sY2[t]=-3.0e38f;
            sm->sAr[t]= 0.0f;
        }
        float ta = tw*th;
        float best = -1.0f; int bn = 0;
        #pragma unroll
        for (int a = 0; a < 9; a++){
            float inter = fminf(tw, c_AW[a]) * fminf(th, c_AH[a]);
            float iou = inter / (ta + c_AW[a]*c_AH[a] - inter);
            if (iou > best){ best = iou; bn = a; }
        }
        if (valid && bn < 3){
            int ii = (int)tx, jj = (int)ty;
            int slot = jj*FF + ii - n0;
            if (slot >= 0 && slot < PXB) atomicMax(&sm->sOwn[bn*PXB + slot], t);
        }
    }
    __syncthreads();

    /* conv thread mapping: a = tid/80 (3), q = (tid%80)/20 (4), g = tid%20 */
    int ca = tid / 80;           /* 0..2 conv anchor; ==3 for idle tail */
    int rq = tid - ca*80;
    int q  = rq / NG;
    int g  = rq - q*NG;
    bool cvt = (ca < 3);
    int nbase = n0 + 8*g;
    bool pvc = cvt && (8*g < npb);
    int nb = pvc ? nbase : n0;

    /* ---- conv: 5 j (one anchor) x 64 ch (one quarter) x 8 px per thread ---- */
    ull acc[5][4];
    #pragma unroll
    for (int t = 0; t < 5; t++)
        #pragma unroll
        for (int p = 0; p < 4; p++) acc[t][p] = 0ULL;

    if (cvt){
        const ulonglong2* xq = reinterpret_cast<const ulonglong2*>(
            xin + (size_t)b*CIN*NPIX) + (size_t)(q*64)*ST4 + (nb >> 2);
        const ull* wbase = &sm->u.w2[ca*5][q*WQ];
        #pragma unroll 2
        for (int c = 0; c < 64; c += 2){
            ulonglong2 xA0 = xq[(size_t)c*ST4];
            ulonglong2 xA1 = xq[(size_t)c*ST4 + 1];
            ulonglong2 xB0 = xq[(size_t)(c+1)*ST4];
            ulonglong2 xB1 = xq[(size_t)(c+1)*ST4 + 1];
            #pragma unroll
            for (int t = 0; t < 5; t++){
                ulonglong2 w = *reinterpret_cast<const ulonglong2*>(
                    wbase + (size_t)t*(4*WQ) + c);
                fma2(acc[t][0], w.x, xA0.x); fma2(acc[t][1], w.x, xA0.y);
                fma2(acc[t][2], w.x, xA1.x); fma2(acc[t][3], w.x, xA1.y);
                fma2(acc[t][0], w.y, xB0.x); fma2(acc[t][1], w.y, xB0.y);
                fma2(acc[t][2], w.y, xB1.x); fma2(acc[t][3], w.y, xB1.y);
            }
        }
    }
    __syncthreads();   /* all w2 reads done -> union becomes part */
    if (cvt){
        #pragma unroll
        for (int t = 0; t < 5; t++)
            #pragma unroll
            for (int p = 0; p < 4; p++)
                sm->u.part[q][ca*5 + t][g][p] = acc[t][p];
    }
    __syncthreads();

    double l_xy=0.0, l_wh=0.0, l_obj=0.0, l_cl=0.0, l_l2=0.0;

    /* ---- each thread tid<npb finalizes ONE pixel, per-anchor ---- */
    if (tid < npb){
        int slot = tid;
        int n = n0 + slot;
        int pg = slot >> 3;
        int pp = (slot >> 1) & 3;
        int hf = slot & 1;
        int h = n / FF, w = n % FF;

        #pragma unroll
        for (int a = 0; a < NA; a++){
            float a5[5];
            #pragma unroll
            for (int t = 0; t < 5; t++){
                int j = a*5 + t;
                ull s01 = add2(sm->u.part[0][j][pg][pp], sm->u.part[1][j][pg][pp]);
                ull s23 = add2(sm->u.part[2][j][pg][pp], sm->u.part[3][j][pg][pp]);
                float2 f = u2f2(add2(s01, s23));
                a5[t] = (hf ? f.y : f.x) + sm->sB[j];
            }
            float s0 = sigf(a5[0]), s1 = sigf(a5[1]), s4 = sigf(a5[4]);
            float px = s0 + (float)w, py = s1 + (float)h;
            float pw = expf(a5[2])*c_MW[a], ph = expf(a5[3])*c_MH[a];
            float bx1 = px - pw*0.5f, by1 = py - ph*0.5f;
            float bx2 = px + pw*0.5f, by2 = py + ph*0.5f;
            float bap = pw*ph;

            bool ign = false;
            #pragma unroll 2
            for (int k = 0; k < KK; k++){
                float dx = fminf(bx2, sm->sX2[k]) - fmaxf(bx1, sm->sX1[k]);
                float dy = fminf(by2, sm->sY2[k]) - fmaxf(by1, sm->sY1[k]);
                float inter = dx*dy;
                bool en = (dx > 0.0f) & (dy > 0.0f);
                ign = ign | (en & (inter > 0.7f*(bap + sm->sAr[k] - inter)));
            }

            int cell = (b*NA + a)*NPIX + n;
            int k = sm->sOwn[a*PXB + slot];
            bool m = (k >= 0);
            float obj = m ? 1.0f : (ign ? 0.0f : 1.0f);
            float o4 = s4 * obj;
            float* d5 = &sm->out5[a][slot][0];

            if (m){
                float tx = sm->sTx[k], ty = sm->sTy[k];
                float tw = sm->sTw[k], th = sm->sTh[k];
                int ii = (int)tx, jj = (int)ty;
                float tfx = tx - (float)ii, tfy = ty - (float)jj;
                float lw = logf(tw / c_MW[a] + 1e-16f);
                float lh = logf(th / c_MH[a] + 1e-16f);
                float sc  = sqrtf(2.0f - tw*th/(float)NPIX);
                float sc2 = sc*sc;
                l_xy += (double)((bce1(s0, tfx) + bce1(s1, tfy)) * sc2);
                float ow2 = a5[2]*sc, ow3 = a5[3]*sc;
                float tw2 = lw*sc, tw3 = lh*sc;
                float d2 = ow2 - tw2, d3 = ow3 - tw3;
                l_wh += 0.5*(double)(d2*d2 + d3*d3);
                l_obj += (double)bce1(o4, 1.0f);
                float e0 = s0 - tfx, e1 = s1 - tfy, e4 = o4 - 1.0f;
                l_l2 += (double)(e0*e0 + e1*e1 + d2*d2 + d3*d3 + e4*e4);
                int idx = atomicAdd(&sm->sCnt, 1);
                sm->sPos[idx] = (cell << 7) | sm->sCls[k];
                d5[0]=s0; d5[1]=s1; d5[2]=ow2; d5[3]=ow3; d5[4]=o4;
            } else {
                l_obj += (double)bce1(o4, 0.0f);
                l_l2  += (double)(o4*o4);
                d5[0]=0.0f; d5[1]=0.0f; d5[2]=0.0f; d5[3]=0.0f; d5[4]=o4;
            }
        }
    }
    __syncthreads();

    /* ---- single-pass coalesced store of the 3 output regions ---- */
    #pragma unroll
    for (int a = 0; a < NA; a++){
        size_t e0 = 6 + ((size_t)((b*NA + a)*NPIX + n0))*NCH;
        float* base = dout + e0;
        int cnt = npb*NCH;
        int pad = (int)((4 - (e0 & 3)) & 3);
        if (pad > cnt) pad = cnt;
        if (tid < pad){
            int cell = tid/NCH, c = tid - cell*NCH;
            base[tid] = (c < 5) ? sm->out5[a][cell][c] : 0.0f;
        }
        int nv = (cnt - pad) >> 2;
        float4* b4 = (float4*)(base + pad);
        for (int j = tid; j < nv; j += TPB){
            int g2 = pad + (j << 2);
            float4 vv;
            { int cell = g2/NCH,     c = g2     - cell*NCH; vv.x = (c < 5) ? sm->out5[a][cell][c] : 0.0f; }
            { int cell = (g2+1)/NCH, c = (g2+1) - cell*NCH; vv.y = (c < 5) ? sm->out5[a][cell][c] : 0.0f; }
            { int cell = (g2+2)/NCH, c = (g2+2) - cell*NCH; vv.z = (c < 5) ? sm->out5[a][cell][c] : 0.0f; }
            { int cell = (g2+3)/NCH, c = (g2+3) - cell*NCH; vv.w = (c < 5) ? sm->out5[a][cell][c] : 0.0f; }
            b4[j] = vv;
        }
        int rem0 = pad + (nv << 2);
        if (rem0 + tid < cnt){
            int g2 = rem0 + tid;
            int cell = g2/NCH, c = g2 - cell*NCH;
            base[g2] = (c < 5) ? sm->out5[a][cell][c] : 0.0f;
        }
    }
    __syncthreads();

    /* ---- class pass: 8 warps x 10 classes per positive ---- */
    {
        int lane = tid & 31, wid = tid >> 5;   /* wid 0..7 */
        int cnt = sm->sCnt;
        for (int qd = 0; qd < cnt; qd++){
            int pk   = sm->sPos[qd];
            int cell = pk >> 7;
            int cls  = pk & 127;
            int a    = (cell / NPIX) % NA;
            int pix  = cell % NPIX;
            for (int i = tid; i < CIN; i += TPB)
                sm->sX[i] = xin[((size_t)b*CIN + i)*NPIX + pix];
            __syncthreads();

            const float* wbase = cw + (size_t)(a*NCH + 5 + wid*10)*CIN;
            float s[10];
            #pragma unroll
            for (int i = 0; i < 10; i++) s[i] = 0.0f;
            #pragma unroll
            for (int j = 0; j < 8; j++){
                float x = sm->sX[lane + 32*j];
                #pragma unroll
                for (int i = 0; i < 10; i++)
                    s[i] += wbase[(size_t)i*CIN + lane + 32*j] * x;
            }
            #pragma unroll
            for (int i = 0; i < 10; i++){
                #pragma unroll
                for (int off = 16; off; off >>= 1)
                    s[i] += __shfl_down_sync(0xffffffffu, s[i], off);
            }
            if (lane == 0){
                float* oc = dout + 6 + (size_t)cell*NCH;
                #pragma unroll
                for (int i = 0; i < 10; i++){
                    int c = wid*10 + i;
                    float raw = s[i] + cb[a*NCH + 5 + c];
                    float sg = sigf(raw);
                    float t = (c == cls) ? 1.0f : 0.0f;
                    l_cl += (double)bce1(sg, t);
                    float d = sg - t;
                    l_l2 += (double)(d*d);
                    oc[5 + c] = sg;
                }
            }
            __syncthreads();
        }
    }

    /* ---- block reduce 5 doubles -> atomicAdd ---- */
    int lane = tid & 31, wid = tid >> 5;
    #pragma unroll
    for (int off = 16; off; off >>= 1){
        l_xy  += __shfl_down_sync(0xffffffffu, l_xy,  off);
        l_wh  += __shfl_down_sync(0xffffffffu, l_wh,  off);
        l_obj += __shfl_down_sync(0xffffffffu, l_obj, off);
        l_cl  += __shfl_down_sync(0xffffffffu, l_cl,  off);
        l_l2  += __shfl_down_sync(0xffffffffu, l_l2,  off);
    }
    if (lane == 0){
        sm->red[0][wid]=l_xy; sm->red[1][wid]=l_wh; sm->red[2][wid]=l_obj;
        sm->red[3][wid]=l_cl; sm->red[4][wid]=l_l2;
    }
    __syncthreads();
    if (tid == 0){
        double a0=0,a1=0,a2s=0,a3=0,a4=0;
        #pragma unroll
        for (int i = 0; i < 8; i++){
            a0+=sm->red[0][i]; a1+=sm->red[1][i]; a2s+=sm->red[2][i];
            a3+=sm->red[3][i]; a4+=sm->red[4][i];
        }
        atomicAdd(&g_acc[0], a0);
        atomicAdd(&g_acc[1], a1);
        atomicAdd(&g_acc[2], a2s);
        atomicAdd(&g_acc[3], a3);
        atomicAdd(&g_acc[4], a4);

        __threadfence();
        unsigned int t = atomicInc(&g_done, TOTB - 1);
        if (t == TOTB - 1){
            double xy = atomicAdd(&g_acc[0], 0.0);
            double wh = atomicAdd(&g_acc[1], 0.0);
            double ob = atomicAdd(&g_acc[2], 0.0);
            double cl = atomicAdd(&g_acc[3], 0.0);
            double l2 = atomicAdd(&g_acc[4], 0.0);
            dout[0] = (float)(xy + wh + ob + cl);
            dout[1] = (float)xy;
            dout[2] = (float)wh;
            dout[3] = (float)ob;
            dout[4] = (float)cl;
            dout[5] = (float)l2;
            g_acc[0]=0.0; g_acc[1]=0.0; g_acc[2]=0.0; g_acc[3]=0.0; g_acc[4]=0.0;
            __threadfence();
        }
    }
}

extern "C" void kernel_launch(void* const* d_in, const int* in_sizes, int n_in,
                              void* d_out, int out_size)
{
    const float* xin    = (const float*)d_in[0];
    const float* labels = (const float*)d_in[1];
    const float* cw     = (const float*)d_in[2];
    const float* cb     = (const float*)d_in[3];
    float* dout = (float*)d_out;

    static int smem_set = 0;
    int smem = (int)sizeof(SMem);
    if (!smem_set){
        cudaFuncSetAttribute(k_main, cudaFuncAttributeMaxDynamicSharedMemorySize, smem);
        smem_set = 1;
    }
    dim3 g(NBLK, BB);   /* 37 x 16 = 592 blocks = exactly 4.0/SM, 32 warps/SM */
    k_main<<<g, TPB, smem>>>(xin, labels, cw, cb, dout);
}

// round 16
// speedup vs baseline: 1.3769x; 1.3769x over previous
#include <cuda_runtime.h>

#define BB 16
#define CIN 256
#define FF 76
#define NPIX (FF*FF)          /* 5776 */
#define NA 3
#define NCH 85
#define KK 50
#define PXB 160               /* pixels per block */
#define TPB 160               /* 5 warps */
#define NGRP 40               /* 4-pixel groups per block */
#define NBLK 37               /* ceil(5776/160) */
#define TOTB (NBLK*BB)        /* 592 = 148*4 exactly */
#define ST2 (NPIX/4)          /* 1444 ulonglong2 per channel */
#define WQ 66                 /* padded quarter stride in ull: 16B-aligned, bank-split */

typedef unsigned long long ull;

__device__ double       g_acc[5];
__device__ unsigned int g_done;

__constant__ float c_AW[9] = {1.25f,2.0f,4.125f,3.75f,7.75f,7.375f,14.5f,19.5f,46.625f};
__constant__ float c_AH[9] = {1.625f,3.75f,2.875f,7.625f,5.625f,14.875f,11.25f,24.75f,40.75f};
__constant__ float c_MW[3] = {1.25f,2.0f,4.125f};
__constant__ float c_MH[3] = {1.625f,3.75f,2.875f};

/* one union region, time-multiplexed: w2 (conv) -> part (combine) -> out5 (store) */
union UShared {
    ull   w2[15][4*WQ];           /* 31680 B, quarter-interleaved+pad */
    ull   part[4][15][NGRP][2];   /* 38400 B */
    float out5[NA][PXB][5];       /*  9600 B */
};
struct SMem {
    UShared u;
    float  sB[15];
    float  sTx[KK], sTy[KK], sTw[KK], sTh[KK];
    float  sX1[KK], sY1[KK], sX2[KK], sY2[KK], sAr[KK];
    int    sCls[KK];
    int    sOwn[NA*PXB];
    int    sPos[KK];
    int    sCnt;
    float  sX[CIN];
    double red[5][5];
};

__device__ __forceinline__ float sigf(float x){ return 1.0f/(1.0f + expf(-x)); }

__device__ __forceinline__ float bce1(float p, float t){
    float pc = fminf(fmaxf(p, 1e-12f), 0.99999988f);
    return -(t*logf(pc) + (1.0f - t)*logf(1.0f - pc));
}

__device__ __forceinline__ void fma2(ull& acc, ull a, ull b){
    asm("fma.rn.f32x2 %0, %1, %2, %0;" : "+l"(acc) : "l"(a), "l"(b));
}
__device__ __forceinline__ ull add2(ull a, ull b){
    ull r; asm("add.rn.f32x2 %0, %1, %2;" : "=l"(r) : "l"(a), "l"(b)); return r;
}
__device__ __forceinline__ float2 u2f2(ull v){
    float2 r; asm("mov.b64 {%0, %1}, %2;" : "=f"(r.x), "=f"(r.y) : "l"(v)); return r;
}

__global__ void __launch_bounds__(TPB, 4)
k_main(const float* __restrict__ xin, const float* __restrict__ labels,
       const float* __restrict__ cw,  const float* __restrict__ cb,
       float* __restrict__ dout)
{
    extern __shared__ __align__(16) char smraw[];
    SMem* sm = reinterpret_cast<SMem*>(smraw);

    int tid = threadIdx.x;
    int b   = blockIdx.y;
    int n0  = blockIdx.x*PXB;
    int npb = NPIX - n0; if (npb > PXB) npb = PXB;   /* 160 or 16, mult of 4 */

    for (int i = tid; i < NA*PXB; i += TPB) sm->sOwn[i] = -1;
    if (tid == 0) sm->sCnt = 0;

    /* weights as (w,w) pairs, quarter-interleaved + padded (phase: w2) */
    for (int i = tid; i < 15*CIN; i += TPB){
        int j = i >> 8, c = i & 255;
        int a = j/5, ch = j%5;
        float w = cw[(a*NCH + ch)*CIN + c];
        float2 p = make_float2(w, w);
        sm->u.w2[j][(c >> 6)*WQ + (c & 63)] = *reinterpret_cast<ull*>(&p);
    }
    if (tid < 15){ int a = tid/5, ch = tid%5; sm->sB[tid] = cb[a*NCH + ch]; }
    if (tid >= 64 && tid < 64 + KK){
        int t = tid - 64;
        const float* L = labels + (b*KK + t)*5;
        float cls=L[0], xc=L[1], yc=L[2], w=L[3], h=L[4];
        bool valid = (cls + xc + yc + w + h) > 0.0f;
        float tx = xc*(float)FF, ty = yc*(float)FF;
        float tw = w *(float)FF, th = h *(float)FF;
        sm->sTx[t]=tx; sm->sTy[t]=ty; sm->sTw[t]=tw; sm->sTh[t]=th;
        sm->sCls[t] = (int)cls;
        if (valid){
            sm->sX1[t]=tx-tw*0.5f; sm->sY1[t]=ty-th*0.5f;
            sm->sX2[t]=tx+tw*0.5f; sm->sY2[t]=ty+th*0.5f;
            sm->sAr[t]=tw*th;
        } else {
            sm->sX1[t]= 3.0e38f; sm->sY1[t]= 3.0e38f;
            sm->sX2[t]=-3.0e38f; sm->sY2[t]=-3.0e38f;
            sm->sAr[t]= 0.0f;
        }
        float ta = tw*th;
        float best = -1.0f; int bn = 0;
        #pragma unroll
        for (int a = 0; a < 9; a++){
            float inter = fminf(tw, c_AW[a]) * fminf(th, c_AH[a]);
            float iou = inter / (ta + c_AW[a]*c_AH[a] - inter);
            if (iou > best){ best = iou; bn = a; }
        }
        if (valid && bn < 3){
            int ii = (int)tx, jj = (int)ty;
            int slot = jj*FF + ii - n0;
            if (slot >= 0 && slot < PXB) atomicMax(&sm->sOwn[bn*PXB + slot], t);
        }
    }
    __syncthreads();

    int q   = tid / NGRP;        /* channel quarter 0..3 (warp-quasi-uniform) */
    int grp = tid - q*NGRP;      /* 4-pixel group 0..39 */
    int nbase = n0 + 4*grp;
    bool pvc = (4*grp < npb);
    int nb = pvc ? nbase : n0;
    double l_xy=0.0, l_wh=0.0, l_obj=0.0, l_cl=0.0, l_l2=0.0;

    /* ---- conv: 4 pixels x 64 channels per thread, f32x2, full unroll ---- */
    ull accA[15], accB[15];
    #pragma unroll
    for (int j = 0; j < 15; j++){ accA[j] = 0ULL; accB[j] = 0ULL; }
    {
        const ulonglong2* xq = reinterpret_cast<const ulonglong2*>(
            xin + (size_t)b*CIN*NPIX + nb) + (size_t)(q*64)*ST2;
        const int wq = q*WQ;
        #pragma unroll
        for (int c = 0; c < 64; c += 4){
            ulonglong2 x0 = xq[(size_t)(c+0)*ST2];
            ulonglong2 x1 = xq[(size_t)(c+1)*ST2];
            ulonglong2 x2 = xq[(size_t)(c+2)*ST2];
            ulonglong2 x3 = xq[(size_t)(c+3)*ST2];
            #pragma unroll
            for (int j = 0; j < 15; j++){
                const ull* wp = &sm->u.w2[j][wq + c];
                ulonglong2 wA = *reinterpret_cast<const ulonglong2*>(wp);
                ulonglong2 wB = *reinterpret_cast<const ulonglong2*>(wp + 2);
                fma2(accA[j], wA.x, x0.x); fma2(accB[j], wA.x, x0.y);
                fma2(accA[j], wA.y, x1.x); fma2(accB[j], wA.y, x1.y);
                fma2(accA[j], wB.x, x2.x); fma2(accB[j], wB.x, x2.y);
                fma2(accA[j], wB.y, x3.x); fma2(accB[j], wB.y, x3.y);
            }
        }
    }
    __syncthreads();   /* all w2 reads done -> union becomes part */
    #pragma unroll
    for (int j = 0; j < 15; j++){
        sm->u.part[q][j][grp][0] = accA[j];
        sm->u.part[q][j][grp][1] = accB[j];
    }
    __syncthreads();

    /* ---- each thread finalizes ONE pixel: n0 + tid ---- */
    bool pvE = (tid < npb);
    float o5r[3][5];

    if (pvE){
        int slot = tid;
        int n = n0 + slot;
        int g2   = slot >> 2;
        int pair = (slot >> 1) & 1;
        int hf   = slot & 1;
        float a2[15];
        #pragma unroll
        for (int j = 0; j < 15; j++){
            ull s01 = add2(sm->u.part[0][j][g2][pair], sm->u.part[1][j][g2][pair]);
            ull s23 = add2(sm->u.part[2][j][g2][pair], sm->u.part[3][j][g2][pair]);
            float2 f = u2f2(add2(s01, s23));
            a2[j] = hf ? f.y : f.x;
        }

        int h = n / FF, w = n % FF;
        float s0[3], s1v[3], s4v[3], r2v[3], r3v[3];
        float bx1[3], by1[3], bx2[3], by2[3], bap[3];
        #pragma unroll
        for (int a = 0; a < NA; a++){
            float r0 = a2[a*5+0] + sm->sB[a*5+0];
            float r1 = a2[a*5+1] + sm->sB[a*5+1];
            float r2 = a2[a*5+2] + sm->sB[a*5+2];
            float r3 = a2[a*5+3] + sm->sB[a*5+3];
            float r4 = a2[a*5+4] + sm->sB[a*5+4];
            s0[a]=sigf(r0); s1v[a]=sigf(r1); s4v[a]=sigf(r4);
            r2v[a]=r2; r3v[a]=r3;
            float px = s0[a] + (float)w, py = s1v[a] + (float)h;
            float pw = expf(r2)*c_MW[a], ph = expf(r3)*c_MH[a];
            bx1[a]=px-pw*0.5f; by1[a]=py-ph*0.5f;
            bx2[a]=px+pw*0.5f; by2[a]=py+ph*0.5f;
            bap[a]=pw*ph;
        }

        /* clamped-IoU ignore test: inter>=0 makes the en predicate unnecessary
           (rhs > 0 always since bap > 0), values identical when en was true */
        bool ig[3] = {false,false,false};
        #pragma unroll 2
        for (int k = 0; k < KK; k++){
            float lx1=sm->sX1[k], ly1=sm->sY1[k];
            float lx2=sm->sX2[k], ly2=sm->sY2[k], ar=sm->sAr[k];
            #pragma unroll
            for (int a = 0; a < NA; a++){
                float dx = fmaxf(fminf(bx2[a], lx2) - fmaxf(bx1[a], lx1), 0.0f);
                float dy = fmaxf(fminf(by2[a], ly2) - fmaxf(by1[a], ly1), 0.0f);
                float inter = dx*dy;
                ig[a] = ig[a] | (inter > 0.7f*(bap[a] + ar - inter));
            }
        }

        #pragma unroll
        for (int a = 0; a < NA; a++){
            int cell = (b*NA + a)*NPIX + n;
            int k = sm->sOwn[a*PXB + slot];
            bool m = (k >= 0);
            float obj = m ? 1.0f : (ig[a] ? 0.0f : 1.0f);
            float o4 = s4v[a] * obj;

            if (m){
                float tx = sm->sTx[k], ty = sm->sTy[k];
                float tw = sm->sTw[k], th = sm->sTh[k];
                int ii = (int)tx, jj = (int)ty;
                float tfx = tx - (float)ii, tfy = ty - (float)jj;
                float lw = logf(tw / c_MW[a] + 1e-16f);
                float lh = logf(th / c_MH[a] + 1e-16f);
                float sc  = sqrtf(2.0f - tw*th/(float)NPIX);
                float sc2 = sc*sc;
                l_xy += (double)((bce1(s0[a], tfx) + bce1(s1v[a], tfy)) * sc2);
                float ow2 = r2v[a]*sc, ow3 = r3v[a]*sc;
                float tw2 = lw*sc, tw3 = lh*sc;
                float d2 = ow2 - tw2, d3 = ow3 - tw3;
                l_wh += 0.5*(double)(d2*d2 + d3*d3);
                l_obj += (double)bce1(o4, 1.0f);
                float e0 = s0[a] - tfx, e1 = s1v[a] - tfy, e4 = o4 - 1.0f;
                l_l2 += (double)(e0*e0 + e1*e1 + d2*d2 + d3*d3 + e4*e4);
                int idx = atomicAdd(&sm->sCnt, 1);
                sm->sPos[idx] = (cell << 7) | sm->sCls[k];
                o5r[a][0]=s0[a]; o5r[a][1]=s1v[a]; o5r[a][2]=ow2; o5r[a][3]=ow3; o5r[a][4]=o4;
            } else {
                l_obj += (double)bce1(o4, 0.0f);
                l_l2  += (double)(o4*o4);
                o5r[a][0]=0.0f; o5r[a][1]=0.0f; o5r[a][2]=0.0f; o5r[a][3]=0.0f; o5r[a][4]=o4;
            }
        }
    }
    __syncthreads();   /* all part reads done -> union becomes out5 */

    if (pvE){
        #pragma unroll
        for (int a = 0; a < NA; a++){
            float* d5 = &sm->u.out5[a][tid][0];
            d5[0]=o5r[a][0]; d5[1]=o5r[a][1]; d5[2]=o5r[a][2];
            d5[3]=o5r[a][3]; d5[4]=o5r[a][4];
        }
    }
    __syncthreads();

    /* ---- single-pass coalesced store of the 3 output regions ---- */
    #pragma unroll
    for (int a = 0; a < NA; a++){
        size_t e0 = 6 + ((size_t)((b*NA + a)*NPIX + n0))*NCH;
        float* base = dout + e0;
        int cnt = npb*NCH;
        int pad = (int)((4 - (e0 & 3)) & 3);
        if (pad > cnt) pad = cnt;
        if (tid < pad){
            int cell = tid/NCH, c = tid - cell*NCH;
            base[tid] = (c < 5) ? sm->u.out5[a][cell][c] : 0.0f;
        }
        int nv = (cnt - pad) >> 2;
        float4* b4 = (float4*)(base + pad);
        for (int j = tid; j < nv; j += TPB){
            int g = pad + (j << 2);
            float4 vv;
            { int cell = g/NCH,     c = g     - cell*NCH; vv.x = (c < 5) ? sm->u.out5[a][cell][c] : 0.0f; }
            { int cell = (g+1)/NCH, c = (g+1) - cell*NCH; vv.y = (c < 5) ? sm->u.out5[a][cell][c] : 0.0f; }
            { int cell = (g+2)/NCH, c = (g+2) - cell*NCH; vv.z = (c < 5) ? sm->u.out5[a][cell][c] : 0.0f; }
            { int cell = (g+3)/NCH, c = (g+3) - cell*NCH; vv.w = (c < 5) ? sm->u.out5[a][cell][c] : 0.0f; }
            b4[j] = vv;
        }
        int rem0 = pad + (nv << 2);
        if (rem0 + tid < cnt){
            int g = rem0 + tid;
            int cell = g/NCH, c = g - cell*NCH;
            base[g] = (c < 5) ? sm->u.out5[a][cell][c] : 0.0f;
        }
    }
    __syncthreads();

    /* ---- class pass: 5 warps x 16 classes per positive ---- */
    {
        int lane = tid & 31, wid = tid >> 5;   /* wid 0..4 */
        int cnt = sm->sCnt;
        for (int qd = 0; qd < cnt; qd++){
            int pk   = sm->sPos[qd];
            int cell = pk >> 7;
            int cls  = pk & 127;
            int a    = (cell / NPIX) % NA;
            int pix  = cell % NPIX;
            for (int i = tid; i < CIN; i += TPB)
                sm->sX[i] = xin[((size_t)b*CIN + i)*NPIX + pix];
            __syncthreads();

            const float* wbase = cw + (size_t)(a*NCH + 5 + wid*16)*CIN;
            float s[16];
            #pragma unroll
            for (int i = 0; i < 16; i++) s[i] = 0.0f;
            #pragma unroll
            for (int j = 0; j < 8; j++){
                float x = sm->sX[lane + 32*j];
                #pragma unroll
                for (int i = 0; i < 16; i++)
                    s[i] += wbase[(size_t)i*CIN + lane + 32*j] * x;
            }
            #pragma unroll
            for (int i = 0; i < 16; i++){
                #pragma unroll
                for (int off = 16; off; off >>= 1)
                    s[i] += __shfl_down_sync(0xffffffffu, s[i], off);
            }
            if (lane == 0){
                float* oc = dout + 6 + (size_t)cell*NCH;
                #pragma unroll
                for (int i = 0; i < 16; i++){
                    int c = wid*16 + i;
                    float raw = s[i] + cb[a*NCH + 5 + c];
                    float sg = sigf(raw);
                    float t = (c == cls) ? 1.0f : 0.0f;
                    l_cl += (double)bce1(sg, t);
                    float d = sg - t;
                    l_l2 += (double)(d*d);
                    oc[5 + c] = sg;
                }
            }
            __syncthreads();
        }
    }

    /* ---- block reduce 5 doubles -> atomicAdd ---- */
    int lane = tid & 31, wid = tid >> 5;
    #pragma unroll
    for (int off = 16; off; off >>= 1){
        l_xy  += __shfl_down_sync(0xffffffffu, l_xy,  off);
        l_wh  += __shfl_down_sync(0xffffffffu, l_wh,  off);
        l_obj += __shfl_down_sync(0xffffffffu, l_obj, off);
        l_cl  += __shfl_down_sync(0xffffffffu, l_cl,  off);
        l_l2  += __shfl_down_sync(0xffffffffu, l_l2,  off);
    }
    if (lane == 0){
        sm->red[0][wid]=l_xy; sm->red[1][wid]=l_wh; sm->red[2][wid]=l_obj;
        sm->red[3][wid]=l_cl; sm->red[4][wid]=l_l2;
    }
    __syncthreads();
    if (tid == 0){
        double a0=0,a1=0,a2s=0,a3=0,a4=0;
        #pragma unroll
        for (int i = 0; i < 5; i++){
            a0+=sm->red[0][i]; a1+=sm->red[1][i]; a2s+=sm->red[2][i];
            a3+=sm->red[3][i]; a4+=sm->red[4][i];
        }
        atomicAdd(&g_acc[0], a0);
        atomicAdd(&g_acc[1], a1);
        atomicAdd(&g_acc[2], a2s);
        atomicAdd(&g_acc[3], a3);
        atomicAdd(&g_acc[4], a4);

        __threadfence();
        unsigned int t = atomicInc(&g_done, TOTB - 1);
        if (t == TOTB - 1){
            double xy = atomicAdd(&g_acc[0], 0.0);
            double wh = atomicAdd(&g_acc[1], 0.0);
            double ob = atomicAdd(&g_acc[2], 0.0);
            double cl = atomicAdd(&g_acc[3], 0.0);
            double l2 = atomicAdd(&g_acc[4], 0.0);
            dout[0] = (float)(xy + wh + ob + cl);
            dout[1] = (float)xy;
            dout[2] = (float)wh;
            dout[3] = (float)ob;
            dout[4] = (float)cl;
            dout[5] = (float)l2;
            g_acc[0]=0.0; g_acc[1]=0.0; g_acc[2]=0.0; g_acc[3]=0.0; g_acc[4]=0.0;
            __threadfence();
        }
    }
}

extern "C" void kernel_launch(void* const* d_in, const int* in_sizes, int n_in,
                              void* d_out, int out_size)
{
    const float* xin    = (const float*)d_in[0];
    const float* labels = (const float*)d_in[1];
    const float* cw     = (const float*)d_in[2];
    const float* cb     = (const float*)d_in[3];
    float* dout = (float*)d_out;

    static int smem_set = 0;
    int smem = (int)sizeof(SMem);
    if (!smem_set){
        cudaFuncSetAttribute(k_main, cudaFuncAttributeMaxDynamicSharedMemorySize, smem);
        smem_set = 1;
    }
    dim3 g(NBLK, BB);   /* 37 x 16 = 592 blocks = exactly 4.0/SM */
    k_main<<<g, TPB, smem>>>(xin, labels, cw, cb, dout);
}